// round 11
// baseline (speedup 1.0000x reference)
#include <cuda_runtime.h>
#include <cuda_fp16.h>
#include <cstdint>
#include <math.h>

#define N_NODES 10000
#define N_EDGES 160000
#define F_DIM   64
#define NHEAD   4
#define N_PAD   10048                  // N rounded up to 64

// ---------------- scratch (device globals) ----------------------------------
// Interleaved fp16 features: g_feat[n*64+t] = {rad01, rad23, tan01, tan23}
__device__ uint4   g_feat[N_NODES * 64];
__device__ float4  g_score_r[N_NODES];     // per-node logit scalars (4 heads)
__device__ float4  g_score_t[N_NODES];
__device__ float   g_vr[NHEAD * F_DIM];    // w_proj @ radial_score
__device__ float   g_vt[NHEAD * F_DIM];
__device__ float2  g_exp2[N_EDGES * 4];    // per (sorted-slot, head): (rexp, texp)
__device__ float   g_scale;
__device__ float   g_tconst[2 * NHEAD];    // tbias, tweight
__device__ int     g_indeg[N_NODES];
__device__ int     g_offs[N_NODES];
__device__ int     g_cursor[N_NODES];
__device__ int     g_se[N_EDGES];          // sorted-by-receiver sender id
__device__ int     g_alloc;
__device__ uint32_t g_wt[8 * 64 * 64];     // pre-converted tf32 weights [bc][f][g]
__device__ uint4   g_xt[N_PAD * 16];       // pre-converted tf32 x [n][f]

__device__ __forceinline__ float softplusf(float z) {
    return z > 20.f ? z : log1pf(__expf(z));
}

__device__ __forceinline__ uint32_t f2tf32(float v) {
    uint32_t u;
    asm("cvt.rna.tf32.f32 %0, %1;" : "=r"(u) : "f"(v));
    return u;
}

__device__ __forceinline__ void mma_tf32(float4& c,
                                         uint32_t a0, uint32_t a1, uint32_t a2, uint32_t a3,
                                         uint32_t b0, uint32_t b1) {
    asm volatile(
        "mma.sync.aligned.m16n8k8.row.col.f32.tf32.tf32.f32 "
        "{%0,%1,%2,%3}, {%4,%5,%6,%7}, {%8,%9}, {%0,%1,%2,%3};"
        : "+f"(c.x), "+f"(c.y), "+f"(c.z), "+f"(c.w)
        : "r"(a0), "r"(a1), "r"(a2), "r"(a3), "r"(b0), "r"(b1));
}

// ---------------- K0: small prep: zero hist, fold vectors, weight cvt --------
__global__ void k_prep(const float* __restrict__ wproj,
                       const float* __restrict__ rW,
                       const float* __restrict__ tW,
                       const float* __restrict__ rs,
                       const float* __restrict__ ts,
                       const float* __restrict__ rdls,
                       const float* __restrict__ tbias,
                       const float* __restrict__ tweight) {
    int i = blockIdx.x * blockDim.x + threadIdx.x;
    int stride = gridDim.x * blockDim.x;
    for (int j = i; j < N_NODES; j += stride) g_indeg[j] = 0;
    if (i == 0) g_alloc = 0;

    // weights -> tf32 (32768 elements)
    for (int j = i; j < 8 * 4096; j += stride) {
        int bc = j >> 12, within = j & 4095;
        const float* src = (bc < 4) ? (rW + bc * 4096) : (tW + (bc - 4) * 4096);
        g_wt[j] = f2tf32(src[within]);
    }

    if (blockIdx.x != 0) return;
    int t = threadIdx.x;               // 0..255 -> (h,f)
    int h = t >> 6, f = t & 63;
    const float* W  = wproj + h * F_DIM * F_DIM + f * F_DIM;
    const float* rv = rs + h * F_DIM;
    const float* tv = ts + h * F_DIM;
    float ar = 0.f, at = 0.f;
#pragma unroll
    for (int g = 0; g < F_DIM; g++) { ar += W[g] * rv[g]; at += W[g] * tv[g]; }
    g_vr[t] = ar;
    g_vt[t] = at;
    if (t == 0) g_scale = softplusf(rdls[0]);
    if (t < NHEAD)          g_tconst[t] = tbias[t];
    else if (t < 2 * NHEAD) g_tconst[t] = tweight[t - NHEAD];
}

// ---------------- K1: in-degree histogram + x tf32 conversion ---------------
__global__ void k_hist(const int* __restrict__ eidx,
                       const float* __restrict__ x) {
    int i = blockIdx.x * blockDim.x + threadIdx.x;
    if (i < N_EDGES) atomicAdd(&g_indeg[eidx[N_EDGES + i]], 1);
    uint32_t* xt = (uint32_t*)g_xt;
    for (int j = i; j < N_NODES * F_DIM; j += N_EDGES) xt[j] = f2tf32(x[j]);
}

// ---------------- K2: range allocation + fp32 scalar scores -----------------
// grid 313x256 = 80128 threads. idx<10000: base alloc. idx<80000: one (n,sub).
__global__ void k_base_score(const float* __restrict__ x) {
    int idx = blockIdx.x * blockDim.x + threadIdx.x;
    if (idx < N_NODES) {
        int b = atomicAdd(&g_alloc, g_indeg[idx]);
        g_offs[idx]   = b;
        g_cursor[idx] = b;
    }
    if (idx < N_NODES * 8) {
        int n = idx >> 3, sub = idx & 7;
        int hh = sub & 3;
        bool isR = sub < 4;
        const float* v = (isR ? g_vr : g_vt) + hh * F_DIM;
        const float* xr = x + n * F_DIM;
        float s = 0.f;
#pragma unroll
        for (int f = 0; f < F_DIM; f++) s += xr[f] * v[f];
        float* dst = isR ? (float*)g_score_r : (float*)g_score_t;
        dst[n * NHEAD + hh] = s;
    }
}

// ---------------- K3: tensor-core projection GEMM (pure) --------------------
// grid (157, 8): blockIdx.y = bc. bc<4 -> radial head bc; else tangential.
#define XS_STRIDE 68
#define WS_STRIDE 72
__global__ void __launch_bounds__(256) k_node_mma() {
    __shared__ uint32_t xs[64 * XS_STRIDE];
    __shared__ uint32_t ws[64 * WS_STRIDE];
    int t  = threadIdx.x;
    int n0 = blockIdx.x * 64;
    int bc = blockIdx.y;                       // 0..7

    // stage x tile (tf32): 1024 uint4, 4 per thread
    const uint4* xsrc = g_xt + n0 * 16;
#pragma unroll
    for (int i = 0; i < 4; i++) {
        int idx4 = i * 256 + t;
        int n = idx4 >> 4, gq = idx4 & 15;
        uint4 v = xsrc[idx4];
        *(uint4*)(xs + n * XS_STRIDE + gq * 4) = v;
    }
    // stage weight tile (tf32): 4 uint4 per thread
    const uint32_t* wsrc = g_wt + bc * 4096;
#pragma unroll
    for (int i = 0; i < 4; i++) {
        int idx4 = i * 256 + t;
        int f = idx4 >> 4, gq = idx4 & 15;
        uint4 v = ((const uint4*)wsrc)[idx4];
        *(uint4*)(ws + f * WS_STRIDE + gq * 4) = v;
    }
    __syncthreads();

    int w = t >> 5, lane = t & 31;
    int g4 = lane >> 2, tig = lane & 3;
    int nt = w & 3;                  // node strip (16 nodes)
    int cb = (w >> 2) * 4;           // first of 4 col tiles (8 cols each)
    const uint32_t* xrow0 = xs + (nt * 16 + g4) * XS_STRIDE;
    const uint32_t* xrow1 = xrow0 + 8 * XS_STRIDE;

    float4 acc[4];
#pragma unroll
    for (int ct = 0; ct < 4; ct++) acc[ct] = make_float4(0.f, 0.f, 0.f, 0.f);
#pragma unroll
    for (int k0 = 0; k0 < 64; k0 += 8) {
        uint32_t a0 = xrow0[k0 + tig];
        uint32_t a1 = xrow1[k0 + tig];
        uint32_t a2 = xrow0[k0 + tig + 4];
        uint32_t a3 = xrow1[k0 + tig + 4];
#pragma unroll
        for (int ct = 0; ct < 4; ct++) {
            int gcol = (cb + ct) * 8 + g4;
            uint32_t b0 = ws[(k0 + tig) * WS_STRIDE + gcol];
            uint32_t b1 = ws[(k0 + tig + 4) * WS_STRIDE + gcol];
            mma_tf32(acc[ct], a0, a1, a2, a3, b0, b1);
        }
    }

    // epilogue into interleaved g_feat: uint4 = {rad01, rad23, tan01, tan23}
    __half2* fw = (__half2*)g_feat;            // 4 half2 words per uint4
    int wordbase = (bc < 4) ? 0 : 2;
    int cbase = (bc & 3) * 64;
    int n_a = n0 + nt * 16 + g4;
    int n_b = n_a + 8;
#pragma unroll
    for (int ct = 0; ct < 4; ct++) {
        int c = cbase + (cb + ct) * 8 + tig * 2;   // even col in [0,256)
        int tcol = c >> 2;                         // thread-col 0..63
        int word = wordbase + ((c & 2) >> 1);
        __half2 h01 = __floats2half2_rn(acc[ct].x, acc[ct].y);
        __half2 h23 = __floats2half2_rn(acc[ct].z, acc[ct].w);
        if (n_a < N_NODES) fw[(n_a * 64 + tcol) * 4 + word] = h01;
        if (n_b < N_NODES) fw[(n_b * 64 + tcol) * 4 + word] = h23;
    }
}

// ---------------- K4: edge logits -> exp, scattered into sorted slots -------
__global__ void k_edge(const int* __restrict__ eidx,
                       const float* __restrict__ elen) {
    int e = blockIdx.x * blockDim.x + threadIdx.x;
    if (e >= N_EDGES) return;
    int s = eidx[e];
    int r = eidx[N_EDGES + e];
    float len = elen[e];

    float4 srs = g_score_r[s], srr = g_score_r[r];
    float4 sts = g_score_t[s], str = g_score_t[r];

    float it0 = 1.f / (softplusf(g_tconst[0] + g_tconst[4] * len) + 1e-4f);
    float it1 = 1.f / (softplusf(g_tconst[1] + g_tconst[5] * len) + 1e-4f);
    float it2 = 1.f / (softplusf(g_tconst[2] + g_tconst[6] * len) + 1e-4f);
    float it3 = 1.f / (softplusf(g_tconst[3] + g_tconst[7] * len) + 1e-4f);
    float sl = g_scale * len;

    float re0 = __expf((srs.x - srr.x - sl) * it0);
    float re1 = __expf((srs.y - srr.y - sl) * it1);
    float re2 = __expf((srs.z - srr.z - sl) * it2);
    float re3 = __expf((srs.w - srr.w - sl) * it3);
    float te0 = __expf(sts.x - str.x);
    float te1 = __expf(sts.y - str.y);
    float te2 = __expf(sts.z - str.z);
    float te3 = __expf(sts.w - str.w);

    int pos = atomicAdd(&g_cursor[r], 1);
    g_se[pos] = s;
    float2* e2 = g_exp2 + pos * 4;
    e2[0] = make_float2(re0, te0);
    e2[1] = make_float2(re1, te1);
    e2[2] = make_float2(re2, te2);
    e2[3] = make_float2(re3, te3);
}

// ---------------- K5: dual-stream gather + normalize + w_out + residual -----
__global__ void __launch_bounds__(64) k_gather(const float* __restrict__ x,
                                               const float* __restrict__ wout,
                                               float* __restrict__ out) {
    __shared__ float4 tmp[64];
    __shared__ float  p[F_DIM];
    int n = blockIdx.x;
    int t = threadIdx.x;
    int h = t >> 4;
    int base = g_offs[n];
    int deg  = g_indeg[n];

    float4 accr = make_float4(0.f, 0.f, 0.f, 0.f);
    float4 acct = make_float4(0.f, 0.f, 0.f, 0.f);
    float sdr = 0.f, sdt = 0.f;

#define GATHER_ONE(J)                                                          \
    {                                                                          \
        int s = g_se[J];                                                       \
        float2 w2 = g_exp2[(J) * 4 + h];                                       \
        float ar = w2.x, at = w2.y;                                            \
        uint4 f4 = g_feat[s * 64 + t];                                         \
        float2 r0 = __half22float2(*(__half2*)&f4.x);                          \
        float2 r1 = __half22float2(*(__half2*)&f4.y);                          \
        float2 t0 = __half22float2(*(__half2*)&f4.z);                          \
        float2 t1 = __half22float2(*(__half2*)&f4.w);                          \
        accr.x += ar * r0.x; accr.y += ar * r0.y;                              \
        accr.z += ar * r1.x; accr.w += ar * r1.y;                              \
        acct.x += at * t0.x; acct.y += at * t0.y;                              \
        acct.z += at * t1.x; acct.w += at * t1.y;                              \
        sdr += ar; sdt += at;                                                  \
    }

    int half1 = deg >> 1;
    int j1 = base, e1 = base + half1;
    int j2 = e1,   e2 = base + deg;
#pragma unroll 2
    for (; j1 < e1; j1++, j2++) {
        GATHER_ONE(j1);
        GATHER_ONE(j2);
    }
    for (; j2 < e2; j2++) GATHER_ONE(j2);
#undef GATHER_ONE

    float4 res = make_float4(0.f, 0.f, 0.f, 0.f);
    if (deg > 0) {
        float ir = 1.f / sdr;
        float it = 1.f / sdt;
        uint4 f4 = g_feat[n * 64 + t];
        float2 r0 = __half22float2(*(__half2*)&f4.x);
        float2 r1 = __half22float2(*(__half2*)&f4.y);
        float2 t0 = __half22float2(*(__half2*)&f4.z);
        float2 t1 = __half22float2(*(__half2*)&f4.w);
        res.x = accr.x * ir + acct.x * it - r0.x - t0.x;
        res.y = accr.y * ir + acct.y * it - r0.y - t0.y;
        res.z = accr.z * ir + acct.z * it - r1.x - t1.x;
        res.w = accr.w * ir + acct.w * it - r1.y - t1.y;
    }
    tmp[t] = res;
    __syncthreads();
    if (t < 16) {
        float4 a = tmp[t], b = tmp[t + 16], c = tmp[t + 32], d = tmp[t + 48];
        p[4 * t + 0] = (a.x + b.x + c.x + d.x) * 0.25f;
        p[4 * t + 1] = (a.y + b.y + c.y + d.y) * 0.25f;
        p[4 * t + 2] = (a.z + b.z + c.z + d.z) * 0.25f;
        p[4 * t + 3] = (a.w + b.w + c.w + d.w) * 0.25f;
    }
    __syncthreads();
    float o = x[n * F_DIM + t];
#pragma unroll
    for (int k = 0; k < F_DIM; k++) o += p[k] * wout[k * F_DIM + t];
    out[n * F_DIM + t] = o;
}

// ---------------- launch -----------------------------------------------------
extern "C" void kernel_launch(void* const* d_in, const int* in_sizes, int n_in,
                              void* d_out, int out_size) {
    const float* x      = (const float*)d_in[0];
    const int*   eidx   = (const int*)d_in[1];
    // d_in[2] = edge_vec : unused by the reference math
    const float* elen   = (const float*)d_in[3];
    const float* wproj  = (const float*)d_in[4];
    const float* rW     = (const float*)d_in[5];
    const float* tW     = (const float*)d_in[6];
    const float* rs     = (const float*)d_in[7];
    const float* ts     = (const float*)d_in[8];
    const float* rdls   = (const float*)d_in[9];
    const float* tbias  = (const float*)d_in[10];
    const float* tweight= (const float*)d_in[11];
    const float* wout   = (const float*)d_in[12];
    float* out = (float*)d_out;

    k_prep<<<40, 256>>>(wproj, rW, tW, rs, ts, rdls, tbias, tweight);
    k_hist<<<(N_EDGES + 255) / 256, 256>>>(eidx, x);
    k_base_score<<<(N_NODES * 8 + 255) / 256, 256>>>(x);
    dim3 ggrid((N_NODES + 63) / 64, 8);
    k_node_mma<<<ggrid, 256>>>();
    k_edge<<<(N_EDGES + 255) / 256, 256>>>(eidx, elen);
    k_gather<<<N_NODES, 64>>>(x, wout, out);
}

// round 12
// speedup vs baseline: 1.1204x; 1.1204x over previous
#include <cuda_runtime.h>
#include <cuda_fp16.h>
#include <cstdint>
#include <math.h>

#define N_NODES 10000
#define N_EDGES 160000
#define F_DIM   64
#define NHEAD   4
#define N_PAD   10048

// ---------------- scratch (device globals; zero-initialized at load) --------
__device__ uint4   g_feat[N_NODES * 64];   // fp16 interleaved {rad01,rad23,tan01,tan23}
__device__ float4  g_score_r[N_NODES];
__device__ float4  g_score_t[N_NODES];
__device__ float   g_vr[NHEAD * F_DIM];
__device__ float   g_vt[NHEAD * F_DIM];
__device__ float   g_scale;
__device__ float   g_tconst[2 * NHEAD];
__device__ int     g_indeg[N_NODES];       // reset by k_gather each pass
__device__ int     g_offs[N_NODES];
__device__ int     g_cursor[N_NODES];
__device__ int     g_se[N_EDGES];          // sorted-by-receiver sender id
__device__ int     g_eid[N_EDGES];         // sorted-by-receiver original edge id
__device__ int     g_alloc;                // reset by k_gather each pass
__device__ uint32_t g_wt[8 * 64 * 64];     // tf32 weights [bc][f][g]
__device__ uint4   g_xt[N_PAD * 16];       // tf32 x [n][f]

__device__ __forceinline__ float softplusf(float z) {
    return z > 20.f ? z : log1pf(__expf(z));
}

__device__ __forceinline__ uint32_t f2tf32(float v) {
    uint32_t u;
    asm("cvt.rna.tf32.f32 %0, %1;" : "=r"(u) : "f"(v));
    return u;
}

__device__ __forceinline__ void mma_tf32(float4& c,
                                         uint32_t a0, uint32_t a1, uint32_t a2, uint32_t a3,
                                         uint32_t b0, uint32_t b1) {
    asm volatile(
        "mma.sync.aligned.m16n8k8.row.col.f32.tf32.tf32.f32 "
        "{%0,%1,%2,%3}, {%4,%5,%6,%7}, {%8,%9}, {%0,%1,%2,%3};"
        : "+f"(c.x), "+f"(c.y), "+f"(c.z), "+f"(c.w)
        : "r"(a0), "r"(a1), "r"(a2), "r"(a3), "r"(b0), "r"(b1));
}

// ---------------- K0: hist + x cvt + weight cvt + vector fold ---------------
// grid 625 x 256 (covers all edges). g_indeg arrives zeroed (init / k_gather).
__global__ void k_pre(const float* __restrict__ x,
                      const int* __restrict__ eidx,
                      const float* __restrict__ wproj,
                      const float* __restrict__ rW,
                      const float* __restrict__ tW,
                      const float* __restrict__ rs,
                      const float* __restrict__ ts,
                      const float* __restrict__ rdls,
                      const float* __restrict__ tbias,
                      const float* __restrict__ tweight) {
    int i = blockIdx.x * blockDim.x + threadIdx.x;
    if (i < N_EDGES) atomicAdd(&g_indeg[eidx[N_EDGES + i]], 1);

    uint32_t* xt = (uint32_t*)g_xt;
    for (int j = i; j < N_NODES * F_DIM; j += N_EDGES) xt[j] = f2tf32(x[j]);
    if (i < 8 * 4096) {
        int bc = i >> 12, within = i & 4095;
        const float* src = (bc < 4) ? (rW + bc * 4096) : (tW + (bc - 4) * 4096);
        g_wt[i] = f2tf32(src[within]);
    }

    if (blockIdx.x != 0) return;
    int t = threadIdx.x;               // 0..255 -> (h,f)
    int h = t >> 6, f = t & 63;
    const float* W  = wproj + h * F_DIM * F_DIM + f * F_DIM;
    const float* rv = rs + h * F_DIM;
    const float* tv = ts + h * F_DIM;
    float ar = 0.f, at = 0.f;
#pragma unroll
    for (int g = 0; g < F_DIM; g++) { ar += W[g] * rv[g]; at += W[g] * tv[g]; }
    g_vr[t] = ar;
    g_vt[t] = at;
    if (t == 0) g_scale = softplusf(rdls[0]);
    if (t < NHEAD)          g_tconst[t] = tbias[t];
    else if (t < 2 * NHEAD) g_tconst[t] = tweight[t - NHEAD];
}

// ---------------- K1: range allocation + fp32 scalar scores -----------------
__global__ void k_base_score(const float* __restrict__ x) {
    int idx = blockIdx.x * blockDim.x + threadIdx.x;
    if (idx < N_NODES) {
        int b = atomicAdd(&g_alloc, g_indeg[idx]);
        g_offs[idx]   = b;
        g_cursor[idx] = b;
    }
    if (idx < N_NODES * 8) {
        int n = idx >> 3, sub = idx & 7;
        int hh = sub & 3;
        bool isR = sub < 4;
        const float* v = (isR ? g_vr : g_vt) + hh * F_DIM;
        const float* xr = x + n * F_DIM;
        float s = 0.f;
#pragma unroll
        for (int f = 0; f < F_DIM; f++) s += xr[f] * v[f];
        float* dst = isR ? (float*)g_score_r : (float*)g_score_t;
        dst[n * NHEAD + hh] = s;
    }
}

// ---------------- K2: tensor-core GEMM + edge sort scatter ------------------
// grid (157, 8). 321536 threads also perform the CSR scatter (1 edge each).
#define XS_STRIDE 68
#define WS_STRIDE 72
__global__ void __launch_bounds__(256) k_node_mma(const int* __restrict__ eidx) {
    __shared__ uint32_t xs[64 * XS_STRIDE];
    __shared__ uint32_t ws[64 * WS_STRIDE];
    int t  = threadIdx.x;
    int n0 = blockIdx.x * 64;
    int bc = blockIdx.y;

    // CSR scatter: one edge per thread across the whole grid
    int gid = (bc * gridDim.x + blockIdx.x) * 256 + t;
    if (gid < N_EDGES) {
        int s = eidx[gid];
        int r = eidx[N_EDGES + gid];
        int pos = atomicAdd(&g_cursor[r], 1);
        g_se[pos]  = s;
        g_eid[pos] = gid;
    }

    // stage x tile (tf32): 1024 uint4, 4 per thread
    const uint4* xsrc = g_xt + n0 * 16;
#pragma unroll
    for (int i = 0; i < 4; i++) {
        int idx4 = i * 256 + t;
        int n = idx4 >> 4, gq = idx4 & 15;
        uint4 v = xsrc[idx4];
        *(uint4*)(xs + n * XS_STRIDE + gq * 4) = v;
    }
    const uint32_t* wsrc = g_wt + bc * 4096;
#pragma unroll
    for (int i = 0; i < 4; i++) {
        int idx4 = i * 256 + t;
        int f = idx4 >> 4, gq = idx4 & 15;
        uint4 v = ((const uint4*)wsrc)[idx4];
        *(uint4*)(ws + f * WS_STRIDE + gq * 4) = v;
    }
    __syncthreads();

    int w = t >> 5, lane = t & 31;
    int g4 = lane >> 2, tig = lane & 3;
    int nt = w & 3;
    int cb = (w >> 2) * 4;
    const uint32_t* xrow0 = xs + (nt * 16 + g4) * XS_STRIDE;
    const uint32_t* xrow1 = xrow0 + 8 * XS_STRIDE;

    float4 acc[4];
#pragma unroll
    for (int ct = 0; ct < 4; ct++) acc[ct] = make_float4(0.f, 0.f, 0.f, 0.f);
#pragma unroll
    for (int k0 = 0; k0 < 64; k0 += 8) {
        uint32_t a0 = xrow0[k0 + tig];
        uint32_t a1 = xrow1[k0 + tig];
        uint32_t a2 = xrow0[k0 + tig + 4];
        uint32_t a3 = xrow1[k0 + tig + 4];
#pragma unroll
        for (int ct = 0; ct < 4; ct++) {
            int gcol = (cb + ct) * 8 + g4;
            uint32_t b0 = ws[(k0 + tig) * WS_STRIDE + gcol];
            uint32_t b1 = ws[(k0 + tig + 4) * WS_STRIDE + gcol];
            mma_tf32(acc[ct], a0, a1, a2, a3, b0, b1);
        }
    }

    __half2* fw = (__half2*)g_feat;
    int wordbase = (bc < 4) ? 0 : 2;
    int cbase = (bc & 3) * 64;
    int n_a = n0 + nt * 16 + g4;
    int n_b = n_a + 8;
#pragma unroll
    for (int ct = 0; ct < 4; ct++) {
        int c = cbase + (cb + ct) * 8 + tig * 2;
        int tcol = c >> 2;
        int word = wordbase + ((c & 2) >> 1);
        __half2 h01 = __floats2half2_rn(acc[ct].x, acc[ct].y);
        __half2 h23 = __floats2half2_rn(acc[ct].z, acc[ct].w);
        if (n_a < N_NODES) fw[(n_a * 64 + tcol) * 4 + word] = h01;
        if (n_b < N_NODES) fw[(n_b * 64 + tcol) * 4 + word] = h23;
    }
}

// ---------------- K3: fused exp + gather + normalize + w_out + residual -----
// 64 threads per node. Chunked: phase A computes <=64 edges' exps (1 edge per
// thread, computed ONCE per edge); phase B accumulates weighted features.
__global__ void __launch_bounds__(64) k_gather(const float* __restrict__ x,
                                               const float* __restrict__ elen,
                                               const float* __restrict__ wout,
                                               float* __restrict__ out) {
    __shared__ int    sm_s[64];
    __shared__ float2 sm_w[64][NHEAD];     // per edge, per head: (rexp, texp)
    __shared__ float4 tmp[64];
    __shared__ float  p[F_DIM];
    int n = blockIdx.x;
    int t = threadIdx.x;
    int h = t >> 4;
    int base = g_offs[n];
    int deg  = g_indeg[n];

    float4 srr = g_score_r[n];
    float4 str = g_score_t[n];
    float tb0 = g_tconst[0], tb1 = g_tconst[1], tb2 = g_tconst[2], tb3 = g_tconst[3];
    float tw0 = g_tconst[4], tw1 = g_tconst[5], tw2 = g_tconst[6], tw3 = g_tconst[7];
    float scale = g_scale;

    float4 accr = make_float4(0.f, 0.f, 0.f, 0.f);
    float4 acct = make_float4(0.f, 0.f, 0.f, 0.f);
    float sdr = 0.f, sdt = 0.f;

    for (int c0 = 0; c0 < deg; c0 += 64) {
        int cnt = min(64, deg - c0);
        if (t < cnt) {
            int j = base + c0 + t;
            int s = g_se[j];
            float len = elen[g_eid[j]];
            float4 srs = g_score_r[s];
            float4 sts = g_score_t[s];
            float it0 = 1.f / (softplusf(tb0 + tw0 * len) + 1e-4f);
            float it1 = 1.f / (softplusf(tb1 + tw1 * len) + 1e-4f);
            float it2 = 1.f / (softplusf(tb2 + tw2 * len) + 1e-4f);
            float it3 = 1.f / (softplusf(tb3 + tw3 * len) + 1e-4f);
            float sl = scale * len;
            sm_s[t] = s;
            sm_w[t][0] = make_float2(__expf((srs.x - srr.x - sl) * it0), __expf(sts.x - str.x));
            sm_w[t][1] = make_float2(__expf((srs.y - srr.y - sl) * it1), __expf(sts.y - str.y));
            sm_w[t][2] = make_float2(__expf((srs.z - srr.z - sl) * it2), __expf(sts.z - str.z));
            sm_w[t][3] = make_float2(__expf((srs.w - srr.w - sl) * it3), __expf(sts.w - str.w));
        }
        __syncthreads();

#define GATHER_ONE(C)                                                          \
        {                                                                      \
            float2 w2 = sm_w[C][h];                                            \
            uint4 f4 = g_feat[sm_s[C] * 64 + t];                               \
            float2 r0 = __half22float2(*(__half2*)&f4.x);                      \
            float2 r1 = __half22float2(*(__half2*)&f4.y);                      \
            float2 t0 = __half22float2(*(__half2*)&f4.z);                      \
            float2 t1 = __half22float2(*(__half2*)&f4.w);                      \
            accr.x += w2.x * r0.x; accr.y += w2.x * r0.y;                      \
            accr.z += w2.x * r1.x; accr.w += w2.x * r1.y;                      \
            acct.x += w2.y * t0.x; acct.y += w2.y * t0.y;                      \
            acct.z += w2.y * t1.x; acct.w += w2.y * t1.y;                      \
            sdr += w2.x; sdt += w2.y;                                          \
        }
        int half1 = cnt >> 1;
        int c1 = 0, c2 = half1;
        for (; c1 < half1; c1++, c2++) {
            GATHER_ONE(c1);
            GATHER_ONE(c2);
        }
        for (; c2 < cnt; c2++) GATHER_ONE(c2);
#undef GATHER_ONE
        __syncthreads();
    }

    float4 res = make_float4(0.f, 0.f, 0.f, 0.f);
    if (deg > 0) {
        float ir = 1.f / sdr;
        float it = 1.f / sdt;
        uint4 f4 = g_feat[n * 64 + t];
        float2 r0 = __half22float2(*(__half2*)&f4.x);
        float2 r1 = __half22float2(*(__half2*)&f4.y);
        float2 t0 = __half22float2(*(__half2*)&f4.z);
        float2 t1 = __half22float2(*(__half2*)&f4.w);
        res.x = accr.x * ir + acct.x * it - r0.x - t0.x;
        res.y = accr.y * ir + acct.y * it - r0.y - t0.y;
        res.z = accr.z * ir + acct.z * it - r1.x - t1.x;
        res.w = accr.w * ir + acct.w * it - r1.y - t1.y;
    }
    tmp[t] = res;
    __syncthreads();
    if (t < 16) {
        float4 a = tmp[t], b = tmp[t + 16], c = tmp[t + 32], d = tmp[t + 48];
        p[4 * t + 0] = (a.x + b.x + c.x + d.x) * 0.25f;
        p[4 * t + 1] = (a.y + b.y + c.y + d.y) * 0.25f;
        p[4 * t + 2] = (a.z + b.z + c.z + d.z) * 0.25f;
        p[4 * t + 3] = (a.w + b.w + c.w + d.w) * 0.25f;
    }
    __syncthreads();
    float o = x[n * F_DIM + t];
#pragma unroll
    for (int k = 0; k < F_DIM; k++) o += p[k] * wout[k * F_DIM + t];
    out[n * F_DIM + t] = o;

    // reset pass-state for the next graph replay
    if (t == 0) {
        g_indeg[n] = 0;
        if (n == 0) g_alloc = 0;
    }
}

// ---------------- launch -----------------------------------------------------
extern "C" void kernel_launch(void* const* d_in, const int* in_sizes, int n_in,
                              void* d_out, int out_size) {
    const float* x      = (const float*)d_in[0];
    const int*   eidx   = (const int*)d_in[1];
    // d_in[2] = edge_vec : unused by the reference math
    const float* elen   = (const float*)d_in[3];
    const float* wproj  = (const float*)d_in[4];
    const float* rW     = (const float*)d_in[5];
    const float* tW     = (const float*)d_in[6];
    const float* rs     = (const float*)d_in[7];
    const float* ts     = (const float*)d_in[8];
    const float* rdls   = (const float*)d_in[9];
    const float* tbias  = (const float*)d_in[10];
    const float* tweight= (const float*)d_in[11];
    const float* wout   = (const float*)d_in[12];
    float* out = (float*)d_out;

    k_pre<<<(N_EDGES + 255) / 256, 256>>>(x, eidx, wproj, rW, tW, rs, ts,
                                          rdls, tbias, tweight);
    k_base_score<<<(N_NODES * 8 + 255) / 256, 256>>>(x);
    dim3 ggrid((N_NODES + 63) / 64, 8);
    k_node_mma<<<ggrid, 256>>>(eidx);
    k_gather<<<N_NODES, 64>>>(x, elen, wout, out);
}

// round 13
// speedup vs baseline: 1.1214x; 1.0009x over previous
#include <cuda_runtime.h>
#include <cuda_fp16.h>
#include <cstdint>
#include <math.h>

#define N_NODES 10000
#define N_EDGES 160000
#define F_DIM   64
#define NHEAD   4
#define N_PAD   10048

// ---------------- scratch (device globals; zero-initialized at load) --------
__device__ uint4   g_feat[N_NODES * 64];   // fp16 interleaved {rad01,rad23,tan01,tan23}
__device__ float4  g_score_r[N_NODES];
__device__ float4  g_score_t[N_NODES];
__device__ float   g_vr[NHEAD * F_DIM];
__device__ float   g_vt[NHEAD * F_DIM];
__device__ float   g_scale;
__device__ float   g_tconst[2 * NHEAD];
__device__ int     g_indeg[N_NODES];       // reset by k_gather each pass
__device__ int     g_offs[N_NODES];
__device__ int     g_cursor[N_NODES];
__device__ int     g_se[N_EDGES];          // sorted-by-receiver sender id
__device__ int     g_eid[N_EDGES];         // sorted-by-receiver original edge id
__device__ int     g_alloc;                // reset by k_gather each pass
__device__ uint32_t g_wt[8 * 64 * 64];     // tf32 weights [bc][f][g]
__device__ uint4   g_xt[N_PAD * 16];       // tf32 x [n][f]

__device__ __forceinline__ float softplusf(float z) {
    return z > 20.f ? z : log1pf(__expf(z));
}

__device__ __forceinline__ uint32_t f2tf32(float v) {
    uint32_t u;
    asm("cvt.rna.tf32.f32 %0, %1;" : "=r"(u) : "f"(v));
    return u;
}

__device__ __forceinline__ void mma_tf32(float4& c,
                                         uint32_t a0, uint32_t a1, uint32_t a2, uint32_t a3,
                                         uint32_t b0, uint32_t b1) {
    asm volatile(
        "mma.sync.aligned.m16n8k8.row.col.f32.tf32.tf32.f32 "
        "{%0,%1,%2,%3}, {%4,%5,%6,%7}, {%8,%9}, {%0,%1,%2,%3};"
        : "+f"(c.x), "+f"(c.y), "+f"(c.z), "+f"(c.w)
        : "r"(a0), "r"(a1), "r"(a2), "r"(a3), "r"(b0), "r"(b1));
}

// ---- packed f32x2 helpers (Blackwell FFMA2 path) ----------------------------
#define PACK2(d, lo, hi) \
    asm("mov.b64 %0, {%1, %2};" : "=l"(d) : "r"(__float_as_uint(lo)), "r"(__float_as_uint(hi)))
#define UNPACK2(lo, hi, s) \
    do { uint32_t _a, _b; \
         asm("mov.b64 {%0, %1}, %2;" : "=r"(_a), "=r"(_b) : "l"(s)); \
         lo = __uint_as_float(_a); hi = __uint_as_float(_b); } while (0)
#define FMA2(d, a, b, c) \
    asm("fma.rn.f32x2 %0, %1, %2, %3;" : "=l"(d) : "l"(a), "l"(b), "l"(c))
#define ADD2(d, a, b) \
    asm("add.rn.f32x2 %0, %1, %2;" : "=l"(d) : "l"(a), "l"(b))

// ---------------- K0: hist + x cvt + weight cvt + vector fold ---------------
__global__ void k_pre(const float* __restrict__ x,
                      const int* __restrict__ eidx,
                      const float* __restrict__ wproj,
                      const float* __restrict__ rW,
                      const float* __restrict__ tW,
                      const float* __restrict__ rs,
                      const float* __restrict__ ts,
                      const float* __restrict__ rdls,
                      const float* __restrict__ tbias,
                      const float* __restrict__ tweight) {
    int i = blockIdx.x * blockDim.x + threadIdx.x;
    if (i < N_EDGES) atomicAdd(&g_indeg[eidx[N_EDGES + i]], 1);

    uint32_t* xt = (uint32_t*)g_xt;
    for (int j = i; j < N_NODES * F_DIM; j += N_EDGES) xt[j] = f2tf32(x[j]);
    if (i < 8 * 4096) {
        int bc = i >> 12, within = i & 4095;
        const float* src = (bc < 4) ? (rW + bc * 4096) : (tW + (bc - 4) * 4096);
        g_wt[i] = f2tf32(src[within]);
    }

    if (blockIdx.x != 0) return;
    int t = threadIdx.x;
    int h = t >> 6, f = t & 63;
    const float* W  = wproj + h * F_DIM * F_DIM + f * F_DIM;
    const float* rv = rs + h * F_DIM;
    const float* tv = ts + h * F_DIM;
    float ar = 0.f, at = 0.f;
#pragma unroll
    for (int g = 0; g < F_DIM; g++) { ar += W[g] * rv[g]; at += W[g] * tv[g]; }
    g_vr[t] = ar;
    g_vt[t] = at;
    if (t == 0) g_scale = softplusf(rdls[0]);
    if (t < NHEAD)          g_tconst[t] = tbias[t];
    else if (t < 2 * NHEAD) g_tconst[t] = tweight[t - NHEAD];
}

// ---------------- K1: range allocation + fp32 scalar scores -----------------
__global__ void k_base_score(const float* __restrict__ x) {
    int idx = blockIdx.x * blockDim.x + threadIdx.x;
    if (idx < N_NODES) {
        int b = atomicAdd(&g_alloc, g_indeg[idx]);
        g_offs[idx]   = b;
        g_cursor[idx] = b;
    }
    if (idx < N_NODES * 8) {
        int n = idx >> 3, sub = idx & 7;
        int hh = sub & 3;
        bool isR = sub < 4;
        const float* v = (isR ? g_vr : g_vt) + hh * F_DIM;
        const float* xr = x + n * F_DIM;
        float s = 0.f;
#pragma unroll
        for (int f = 0; f < F_DIM; f++) s += xr[f] * v[f];
        float* dst = isR ? (float*)g_score_r : (float*)g_score_t;
        dst[n * NHEAD + hh] = s;
    }
}

// ---------------- K2: tensor-core GEMM + edge sort scatter ------------------
#define XS_STRIDE 68
#define WS_STRIDE 72
__global__ void __launch_bounds__(256) k_node_mma(const int* __restrict__ eidx) {
    __shared__ uint32_t xs[64 * XS_STRIDE];
    __shared__ uint32_t ws[64 * WS_STRIDE];
    int t  = threadIdx.x;
    int n0 = blockIdx.x * 64;
    int bc = blockIdx.y;

    // CSR scatter: one edge per thread across the whole grid
    int gid = (bc * gridDim.x + blockIdx.x) * 256 + t;
    if (gid < N_EDGES) {
        int s = eidx[gid];
        int r = eidx[N_EDGES + gid];
        int pos = atomicAdd(&g_cursor[r], 1);
        g_se[pos]  = s;
        g_eid[pos] = gid;
    }

    const uint4* xsrc = g_xt + n0 * 16;
#pragma unroll
    for (int i = 0; i < 4; i++) {
        int idx4 = i * 256 + t;
        int n = idx4 >> 4, gq = idx4 & 15;
        uint4 v = xsrc[idx4];
        *(uint4*)(xs + n * XS_STRIDE + gq * 4) = v;
    }
    const uint32_t* wsrc = g_wt + bc * 4096;
#pragma unroll
    for (int i = 0; i < 4; i++) {
        int idx4 = i * 256 + t;
        int f = idx4 >> 4, gq = idx4 & 15;
        uint4 v = ((const uint4*)wsrc)[idx4];
        *(uint4*)(ws + f * WS_STRIDE + gq * 4) = v;
    }
    __syncthreads();

    int w = t >> 5, lane = t & 31;
    int g4 = lane >> 2, tig = lane & 3;
    int nt = w & 3;
    int cb = (w >> 2) * 4;
    const uint32_t* xrow0 = xs + (nt * 16 + g4) * XS_STRIDE;
    const uint32_t* xrow1 = xrow0 + 8 * XS_STRIDE;

    float4 acc[4];
#pragma unroll
    for (int ct = 0; ct < 4; ct++) acc[ct] = make_float4(0.f, 0.f, 0.f, 0.f);
#pragma unroll
    for (int k0 = 0; k0 < 64; k0 += 8) {
        uint32_t a0 = xrow0[k0 + tig];
        uint32_t a1 = xrow1[k0 + tig];
        uint32_t a2 = xrow0[k0 + tig + 4];
        uint32_t a3 = xrow1[k0 + tig + 4];
#pragma unroll
        for (int ct = 0; ct < 4; ct++) {
            int gcol = (cb + ct) * 8 + g4;
            uint32_t b0 = ws[(k0 + tig) * WS_STRIDE + gcol];
            uint32_t b1 = ws[(k0 + tig + 4) * WS_STRIDE + gcol];
            mma_tf32(acc[ct], a0, a1, a2, a3, b0, b1);
        }
    }

    __half2* fw = (__half2*)g_feat;
    int wordbase = (bc < 4) ? 0 : 2;
    int cbase = (bc & 3) * 64;
    int n_a = n0 + nt * 16 + g4;
    int n_b = n_a + 8;
#pragma unroll
    for (int ct = 0; ct < 4; ct++) {
        int c = cbase + (cb + ct) * 8 + tig * 2;
        int tcol = c >> 2;
        int word = wordbase + ((c & 2) >> 1);
        __half2 h01 = __floats2half2_rn(acc[ct].x, acc[ct].y);
        __half2 h23 = __floats2half2_rn(acc[ct].z, acc[ct].w);
        if (n_a < N_NODES) fw[(n_a * 64 + tcol) * 4 + word] = h01;
        if (n_b < N_NODES) fw[(n_b * 64 + tcol) * 4 + word] = h23;
    }
}

// ---------------- K3: fused exp + packed-f32x2 gather + w_out + residual ----
__global__ void __launch_bounds__(64) k_gather(const float* __restrict__ x,
                                               const float* __restrict__ elen,
                                               const float* __restrict__ wout,
                                               float* __restrict__ out) {
    __shared__ int    sm_s[64];
    __shared__ float2 sm_w[64][NHEAD];
    __shared__ float4 tmp[64];
    __shared__ float  p[F_DIM];
    int n = blockIdx.x;
    int t = threadIdx.x;
    int h = t >> 4;
    int base = g_offs[n];
    int deg  = g_indeg[n];

    float4 srr = g_score_r[n];
    float4 str = g_score_t[n];
    float tb0 = g_tconst[0], tb1 = g_tconst[1], tb2 = g_tconst[2], tb3 = g_tconst[3];
    float tw0 = g_tconst[4], tw1 = g_tconst[5], tw2 = g_tconst[6], tw3 = g_tconst[7];
    float scale = g_scale;

    // packed accumulators
    unsigned long long accr01 = 0, accr23 = 0, acct01 = 0, acct23 = 0, sd2 = 0;

    for (int c0 = 0; c0 < deg; c0 += 64) {
        int cnt = min(64, deg - c0);
        if (t < cnt) {
            int j = base + c0 + t;
            int s = g_se[j];
            float len = elen[g_eid[j]];
            float4 srs = g_score_r[s];
            float4 sts = g_score_t[s];
            float it0 = 1.f / (softplusf(tb0 + tw0 * len) + 1e-4f);
            float it1 = 1.f / (softplusf(tb1 + tw1 * len) + 1e-4f);
            float it2 = 1.f / (softplusf(tb2 + tw2 * len) + 1e-4f);
            float it3 = 1.f / (softplusf(tb3 + tw3 * len) + 1e-4f);
            float sl = scale * len;
            sm_s[t] = s;
            sm_w[t][0] = make_float2(__expf((srs.x - srr.x - sl) * it0), __expf(sts.x - str.x));
            sm_w[t][1] = make_float2(__expf((srs.y - srr.y - sl) * it1), __expf(sts.y - str.y));
            sm_w[t][2] = make_float2(__expf((srs.z - srr.z - sl) * it2), __expf(sts.z - str.z));
            sm_w[t][3] = make_float2(__expf((srs.w - srr.w - sl) * it3), __expf(sts.w - str.w));
        }
        __syncthreads();

#define GATHER_ONE(C)                                                          \
        {                                                                      \
            float2 w2 = sm_w[C][h];                                            \
            uint4 f4 = g_feat[sm_s[C] * 64 + t];                               \
            float2 r0 = __half22float2(*(__half2*)&f4.x);                      \
            float2 r1 = __half22float2(*(__half2*)&f4.y);                      \
            float2 t0 = __half22float2(*(__half2*)&f4.z);                      \
            float2 t1 = __half22float2(*(__half2*)&f4.w);                      \
            unsigned long long r01, r23, t01, t23, wr2, wt2, ww2;              \
            PACK2(r01, r0.x, r0.y);  PACK2(r23, r1.x, r1.y);                   \
            PACK2(t01, t0.x, t0.y);  PACK2(t23, t1.x, t1.y);                   \
            PACK2(wr2, w2.x, w2.x);  PACK2(wt2, w2.y, w2.y);                   \
            PACK2(ww2, w2.x, w2.y);                                            \
            FMA2(accr01, r01, wr2, accr01);                                    \
            FMA2(accr23, r23, wr2, accr23);                                    \
            FMA2(acct01, t01, wt2, acct01);                                    \
            FMA2(acct23, t23, wt2, acct23);                                    \
            ADD2(sd2, sd2, ww2);                                               \
        }
        int half1 = cnt >> 1;
        int c1 = 0, c2 = half1;
        for (; c1 < half1; c1++, c2++) {
            GATHER_ONE(c1);
            GATHER_ONE(c2);
        }
        for (; c2 < cnt; c2++) GATHER_ONE(c2);
#undef GATHER_ONE
        __syncthreads();
    }

    float4 accr, acct;
    UNPACK2(accr.x, accr.y, accr01);
    UNPACK2(accr.z, accr.w, accr23);
    UNPACK2(acct.x, acct.y, acct01);
    UNPACK2(acct.z, acct.w, acct23);
    float sdr, sdt;
    UNPACK2(sdr, sdt, sd2);

    float4 res = make_float4(0.f, 0.f, 0.f, 0.f);
    if (deg > 0) {
        float ir = 1.f / sdr;
        float it = 1.f / sdt;
        uint4 f4 = g_feat[n * 64 + t];
        float2 r0 = __half22float2(*(__half2*)&f4.x);
        float2 r1 = __half22float2(*(__half2*)&f4.y);
        float2 t0 = __half22float2(*(__half2*)&f4.z);
        float2 t1 = __half22float2(*(__half2*)&f4.w);
        res.x = accr.x * ir + acct.x * it - r0.x - t0.x;
        res.y = accr.y * ir + acct.y * it - r0.y - t0.y;
        res.z = accr.z * ir + acct.z * it - r1.x - t1.x;
        res.w = accr.w * ir + acct.w * it - r1.y - t1.y;
    }
    tmp[t] = res;
    __syncthreads();
    if (t < 16) {
        float4 a = tmp[t], b = tmp[t + 16], c = tmp[t + 32], d = tmp[t + 48];
        p[4 * t + 0] = (a.x + b.x + c.x + d.x) * 0.25f;
        p[4 * t + 1] = (a.y + b.y + c.y + d.y) * 0.25f;
        p[4 * t + 2] = (a.z + b.z + c.z + d.z) * 0.25f;
        p[4 * t + 3] = (a.w + b.w + c.w + d.w) * 0.25f;
    }
    __syncthreads();

    // GEMV with packed FMA over k-pairs
    unsigned long long o2 = 0;
#pragma unroll
    for (int k = 0; k < F_DIM; k += 2) {
        unsigned long long p2, w2p;
        PACK2(p2, p[k], p[k + 1]);
        PACK2(w2p, wout[k * F_DIM + t], wout[(k + 1) * F_DIM + t]);
        FMA2(o2, p2, w2p, o2);
    }
    float oa, ob;
    UNPACK2(oa, ob, o2);
    out[n * F_DIM + t] = x[n * F_DIM + t] + oa + ob;

    // reset pass-state for the next graph replay
    if (t == 0) {
        g_indeg[n] = 0;
        if (n == 0) g_alloc = 0;
    }
}

// ---------------- launch -----------------------------------------------------
extern "C" void kernel_launch(void* const* d_in, const int* in_sizes, int n_in,
                              void* d_out, int out_size) {
    const float* x      = (const float*)d_in[0];
    const int*   eidx   = (const int*)d_in[1];
    // d_in[2] = edge_vec : unused by the reference math
    const float* elen   = (const float*)d_in[3];
    const float* wproj  = (const float*)d_in[4];
    const float* rW     = (const float*)d_in[5];
    const float* tW     = (const float*)d_in[6];
    const float* rs     = (const float*)d_in[7];
    const float* ts     = (const float*)d_in[8];
    const float* rdls   = (const float*)d_in[9];
    const float* tbias  = (const float*)d_in[10];
    const float* tweight= (const float*)d_in[11];
    const float* wout   = (const float*)d_in[12];
    float* out = (float*)d_out;

    k_pre<<<(N_EDGES + 255) / 256, 256>>>(x, eidx, wproj, rW, tW, rs, ts,
                                          rdls, tbias, tweight);
    k_base_score<<<(N_NODES * 8 + 255) / 256, 256>>>(x);
    dim3 ggrid((N_NODES + 63) / 64, 8);
    k_node_mma<<<ggrid, 256>>>(eidx);
    k_gather<<<N_NODES, 64>>>(x, elen, wout, out);
}